// round 9
// baseline (speedup 1.0000x reference)
#include <cuda_runtime.h>
#include <cuda_bf16.h>
#include <math.h>
#include <stdint.h>

#define WIN_LEN 400
#define WIN_INC 100
#define NFREQ   257
#define NBATCH  16
#define NSAMP   160000
#define NFRAMES 1603
#define PADL    300
#define EPSF    1.1920928955078125e-07f

#define KPAD    416             // 13 * 32
#define NKCH    13
#define MROWS   512             // 256 bins x (real, imag)
#define NTILES  13              // ceil(1603/128)
#define XSTRIDE 166848
#define NTHREADS 256

#define TILE_B  8192            // 128 rows x 64 bytes (32 bf16)
#define NLVL    3
#define STAGE_B (2 * NLVL * TILE_B)   // A0..A2, X0..X2
#define NSTAGE  3
#define DYN_SMEM (NSTAGE * STAGE_B)   // 144 KB

// Prepacked operands (bf16 3-level split: v ~= l0 + l1 + l2)
// A row m: block = m/16, r = m%16; bin = block*8 + (r&7); r<8 real, r>=8 imag
__device__ __align__(16) __nv_bfloat16 g_A[NLVL][MROWS][KPAD];
__device__ __align__(16) __nv_bfloat16 g_X[NLVL][NBATCH][XSTRIDE];

// ---------------- helpers ----------------
__device__ __forceinline__ uint32_t smem_u32(const void* p) {
    uint32_t a;
    asm("{ .reg .u64 t; cvta.to.shared.u64 t, %1; cvt.u32.u64 %0, t; }"
        : "=r"(a) : "l"(p));
    return a;
}
__device__ __forceinline__ void cp16(uint32_t dst, const void* src) {
    asm volatile("cp.async.cg.shared.global [%0], [%1], 16;"
                 :: "r"(dst), "l"(__cvta_generic_to_global(src)) : "memory");
}
__device__ __forceinline__ void cp8(uint32_t dst, const void* src) {
    asm volatile("cp.async.ca.shared.global [%0], [%1], 8;"
                 :: "r"(dst), "l"(__cvta_generic_to_global(src)) : "memory");
}
__device__ __forceinline__ void ldsm4(uint32_t* r, uint32_t addr) {
    asm volatile("ldmatrix.sync.aligned.m8n8.x4.shared.b16 {%0,%1,%2,%3}, [%4];"
                 : "=r"(r[0]), "=r"(r[1]), "=r"(r[2]), "=r"(r[3]) : "r"(addr));
}
__device__ __forceinline__ void ldsm2(uint32_t* r, uint32_t addr) {
    asm volatile("ldmatrix.sync.aligned.m8n8.x2.shared.b16 {%0,%1}, [%2];"
                 : "=r"(r[0]), "=r"(r[1]) : "r"(addr));
}
__device__ __forceinline__ void mma16816(float* c, const uint32_t* a, const uint32_t* b) {
    asm volatile(
        "mma.sync.aligned.m16n8k16.row.col.f32.bf16.bf16.f32 "
        "{%0,%1,%2,%3}, {%4,%5,%6,%7}, {%8,%9}, {%0,%1,%2,%3};"
        : "+f"(c[0]), "+f"(c[1]), "+f"(c[2]), "+f"(c[3])
        : "r"(a[0]), "r"(a[1]), "r"(a[2]), "r"(a[3]), "r"(b[0]), "r"(b[1]));
}

// ---------------- prep kernels ----------------
__global__ void build_A_kernel(const float* __restrict__ w) {
    int idx = blockIdx.x * blockDim.x + threadIdx.x;
    if (idx >= MROWS * KPAD) return;
    int m = idx / KPAD, k = idx % KPAD;
    int blk = m >> 4, r = m & 15;
    int bin = blk * 8 + (r & 7);
    int src_row = (r >= 8) ? (NFREQ + bin) : bin;
    float v = (k < WIN_LEN) ? w[(size_t)src_row * WIN_LEN + k] : 0.0f;
    __nv_bfloat16 h = __float2bfloat16(v);
    float rem = v - __bfloat162float(h);
    __nv_bfloat16 mm = __float2bfloat16(rem);
    __nv_bfloat16 l = __float2bfloat16(rem - __bfloat162float(mm));
    g_A[0][m][k] = h; g_A[1][m][k] = mm; g_A[2][m][k] = l;
}

__global__ void build_X_kernel(const float* __restrict__ x) {
    int idx = blockIdx.x * blockDim.x + threadIdx.x;
    if (idx >= NBATCH * XSTRIDE) return;
    int b = idx / XSTRIDE, p = idx % XSTRIDE, s = p - PADL;
    float v = (s >= 0 && s < NSAMP) ? x[(size_t)b * NSAMP + s] : 0.0f;
    __nv_bfloat16 h = __float2bfloat16(v);
    float rem = v - __bfloat162float(h);
    __nv_bfloat16 mm = __float2bfloat16(rem);
    __nv_bfloat16 l = __float2bfloat16(rem - __bfloat162float(mm));
    g_X[0][b][p] = h; g_X[1][b][p] = mm; g_X[2][b][p] = l;
}

// Nyquist bin (k = 256), fp32 SIMT — tiny.
__global__ void nyq_kernel(const float* __restrict__ x, const float* __restrict__ w,
                           float* __restrict__ out) {
    int t = blockIdx.x * blockDim.x + threadIdx.x;
    int b = blockIdx.y;
    if (t >= NFRAMES) return;
    const float* wr = w + (size_t)256 * WIN_LEN;
    const float* wi = w + (size_t)513 * WIN_LEN;
    const float* xb = x + (size_t)b * NSAMP;
    int p0 = t * WIN_INC - PADL;
    float r = 0.0f, im = 0.0f;
#pragma unroll 4
    for (int n = 0; n < WIN_LEN; n++) {
        int p = p0 + n;
        float xv = (p >= 0 && p < NSAMP) ? __ldg(xb + p) : 0.0f;
        r  = fmaf(xv, __ldg(wr + n), r);
        im = fmaf(xv, __ldg(wi + n), im);
    }
    float mag = sqrtf(fmaxf(fmaf(r, r, im * im), EPSF));
    float ph  = atan2f(im + EPSF, r + EPSF);
    size_t poff = (size_t)NBATCH * NFREQ * NFRAMES;
    size_t o = ((size_t)b * NFREQ + 256) * NFRAMES + t;
    out[o] = mag;
    out[o + poff] = ph;
}

// ---------------- main MMA kernel ----------------
__device__ __forceinline__ void load_chunk(uint32_t sb, int stage, int kc,
        const __nv_bfloat16* A0, const __nv_bfloat16* X0, int b_off, int tid)
{
    uint32_t st = sb + stage * STAGE_B;
    int k0 = kc * 32;
    const size_t ALVL = (size_t)MROWS * KPAD;
    const size_t XLVL = (size_t)NBATCH * XSTRIDE;
    // A tiles: 128 rows x 32 bf16, 16B granules
#pragma unroll
    for (int it = 0; it < 2; it++) {
        int op = tid + it * NTHREADS;        // 512 ops
        int row = op >> 2, unit = op & 3;
        uint32_t dst = st + row * 64 + (((unit) ^ (row & 3)) << 4);
        const __nv_bfloat16* src = A0 + (size_t)row * KPAD + k0 + unit * 8;
#pragma unroll
        for (int lvl = 0; lvl < NLVL; lvl++)
            cp16(dst + lvl * TILE_B, src + lvl * ALVL);
    }
    // X tiles: 128 rows x 32 bf16, 8B granules (200B row stride)
#pragma unroll
    for (int it = 0; it < 4; it++) {
        int op = tid + it * NTHREADS;        // 1024 ops
        int row = op >> 3, h8 = op & 7;
        int unit = h8 >> 1, sub = (h8 & 1) << 3;
        uint32_t dst = st + row * 64 + (((unit) ^ (row & 3)) << 4) + sub
                     + NLVL * TILE_B;
        const __nv_bfloat16* src = X0 + (size_t)row * WIN_INC + k0 + h8 * 4;
#pragma unroll
        for (int lvl = 0; lvl < NLVL; lvl++)
            cp8(dst + lvl * TILE_B, src + lvl * XLVL);
    }
    asm volatile("cp.async.commit_group;" ::: "memory");
}

__global__ void __launch_bounds__(NTHREADS)
stft_mma(float* __restrict__ out) {
    extern __shared__ __align__(128) char smdyn[];
    uint32_t sb = smem_u32(smdyn);
    const int tid = threadIdx.x;
    const int lane = tid & 31, warp = tid >> 5;
    const int mwarp = warp & 3, nwarp = warp >> 2;
    const int mx = blockIdx.x, nt = blockIdx.y, b = blockIdx.z;
    const int m0 = mx * 128, t0 = nt * 128;

    const __nv_bfloat16* A0 = &g_A[0][m0][0];
    const __nv_bfloat16* X0 = &g_X[0][b][(size_t)t0 * WIN_INC];

    float c[2][8][4];
#pragma unroll
    for (int im = 0; im < 2; im++)
#pragma unroll
        for (int jn = 0; jn < 8; jn++)
#pragma unroll
            for (int q = 0; q < 4; q++) c[im][jn][q] = 0.0f;

    load_chunk(sb, 0, 0, A0, X0, 0, tid);
    load_chunk(sb, 1, 1, A0, X0, 0, tid);

    const int arow0 = mwarp * 32 + (lane & 15);
    const int acol  = lane >> 4;
    const int brow0 = nwarp * 64 + (lane & 7);
    const int bsel  = (lane >> 3) & 1;

    for (int kc = 0; kc < NKCH; kc++) {
        if (kc + 2 < NKCH) {
            load_chunk(sb, (kc + 2) % NSTAGE, kc + 2, A0, X0, 0, tid);
            asm volatile("cp.async.wait_group 2;" ::: "memory");
        } else if (kc + 1 < NKCH) {
            asm volatile("cp.async.wait_group 1;" ::: "memory");
        } else {
            asm volatile("cp.async.wait_group 0;" ::: "memory");
        }
        __syncthreads();

        uint32_t st = sb + (kc % NSTAGE) * STAGE_B;
#pragma unroll
        for (int kh = 0; kh < 2; kh++) {
            uint32_t af[NLVL][2][4];
#pragma unroll
            for (int im = 0; im < 2; im++) {
                int row = arow0 + im * 16;
                uint32_t unit = (uint32_t)(((kh << 1) | acol) ^ (row & 3));
                uint32_t addr = st + row * 64 + (unit << 4);
#pragma unroll
                for (int lvl = 0; lvl < NLVL; lvl++)
                    ldsm4(af[lvl][im], addr + lvl * TILE_B);
            }
#pragma unroll
            for (int jn = 0; jn < 8; jn++) {
                int row = brow0 + jn * 8;
                uint32_t unit = (uint32_t)(((kh << 1) | bsel) ^ (row & 3));
                uint32_t baddr = st + NLVL * TILE_B + row * 64 + (unit << 4);
                uint32_t bf[NLVL][2];
#pragma unroll
                for (int lvl = 0; lvl < NLVL; lvl++)
                    ldsm2(bf[lvl], baddr + lvl * TILE_B);
#pragma unroll
                for (int im = 0; im < 2; im++) {
                    mma16816(c[im][jn], af[0][im], bf[0]);   // h*h
                    mma16816(c[im][jn], af[0][im], bf[1]);   // h*m
                    mma16816(c[im][jn], af[1][im], bf[0]);   // m*h
                    mma16816(c[im][jn], af[0][im], bf[2]);   // h*l
                    mma16816(c[im][jn], af[2][im], bf[0]);   // l*h
                    mma16816(c[im][jn], af[1][im], bf[1]);   // m*m
                }
            }
        }
        __syncthreads();
    }

    // ---- epilogue: (c0,c2) = (real,imag) frame f; (c1,c3) = frame f+1 ----
    const size_t poff = (size_t)NBATCH * NFREQ * NFRAMES;
#pragma unroll
    for (int im = 0; im < 2; im++) {
        int bin = (mx * 8 + mwarp * 2 + im) * 8 + (lane >> 2);
        size_t rowo = ((size_t)b * NFREQ + bin) * NFRAMES;
#pragma unroll
        for (int jn = 0; jn < 8; jn++) {
            int fr = t0 + nwarp * 64 + jn * 8 + ((lane & 3) << 1);
            float r0 = c[im][jn][0], r1 = c[im][jn][1];
            float i0 = c[im][jn][2], i1 = c[im][jn][3];
            if (fr < NFRAMES) {
                out[rowo + fr] = sqrtf(fmaxf(fmaf(r0, r0, i0 * i0), EPSF));
                out[rowo + fr + poff] = atan2f(i0 + EPSF, r0 + EPSF);
            }
            if (fr + 1 < NFRAMES) {
                out[rowo + fr + 1] = sqrtf(fmaxf(fmaf(r1, r1, i1 * i1), EPSF));
                out[rowo + fr + 1 + poff] = atan2f(i1 + EPSF, r1 + EPSF);
            }
        }
    }
}

extern "C" void kernel_launch(void* const* d_in, const int* in_sizes, int n_in,
                              void* d_out, int out_size) {
    const float* x = (const float*)d_in[0];
    const float* w = (const float*)d_in[1];
    if (n_in >= 2 && in_sizes[0] == 2 * NFREQ * WIN_LEN) {
        w = (const float*)d_in[0];
        x = (const float*)d_in[1];
    }
    float* out = (float*)d_out;

    cudaFuncSetAttribute(stft_mma,
                         cudaFuncAttributeMaxDynamicSharedMemorySize, DYN_SMEM);

    build_A_kernel<<<(MROWS * KPAD + 255) / 256, 256>>>(w);
    build_X_kernel<<<(NBATCH * XSTRIDE + 255) / 256, 256>>>(x);
    nyq_kernel<<<dim3(NTILES, NBATCH), 128>>>(x, w, out);
    stft_mma<<<dim3(4, NTILES, NBATCH), NTHREADS, DYN_SMEM>>>(out);
}

// round 11
// speedup vs baseline: 1.1396x; 1.1396x over previous
#include <cuda_runtime.h>
#include <cuda_bf16.h>
#include <math.h>
#include <stdint.h>

#define WIN_LEN 400
#define WIN_INC 100
#define NFREQ   257
#define NBATCH  16
#define NSAMP   160000
#define NFRAMES 1603
#define PADL    300
#define EPSF    1.1920928955078125e-07f

#define KPAD    416             // 13 * 32
#define NKCH    13
#define MROWS   512             // 256 bins x (real, imag)
#define NTILES  13              // ceil(1603/128)
#define XSTRIDE 166848
#define NTHREADS 256

#define TILE_B  8192            // 128 rows x 64 bytes (32 bf16)
#define NLVL    3
#define STAGE_B (2 * NLVL * TILE_B)   // 48 KB
#define NSTAGE  2
#define DYN_SMEM (NSTAGE * STAGE_B)   // 96 KB -> 2 CTAs/SM

// bf16 3-level split: v ~= l0 + l1 + l2 (~24 mantissa bits)
// A row m: block = m/16, r = m%16; bin = block*8 + (r&7); r<8 real, r>=8 imag
__device__ __align__(16) __nv_bfloat16 g_A[NLVL][MROWS][KPAD];
__device__ __align__(16) __nv_bfloat16 g_X[NLVL][NBATCH][XSTRIDE];

#define ALVL ((size_t)MROWS * KPAD)
#define XLVL ((size_t)NBATCH * XSTRIDE)

// ---------------- helpers ----------------
__device__ __forceinline__ uint32_t smem_u32(const void* p) {
    uint32_t a;
    asm("{ .reg .u64 t; cvta.to.shared.u64 t, %1; cvt.u32.u64 %0, t; }"
        : "=r"(a) : "l"(p));
    return a;
}
__device__ __forceinline__ void cp16(uint32_t dst, const void* src) {
    asm volatile("cp.async.cg.shared.global [%0], [%1], 16;"
                 :: "r"(dst), "l"(__cvta_generic_to_global(src)) : "memory");
}
__device__ __forceinline__ void cp8(uint32_t dst, const void* src) {
    asm volatile("cp.async.ca.shared.global [%0], [%1], 8;"
                 :: "r"(dst), "l"(__cvta_generic_to_global(src)) : "memory");
}
__device__ __forceinline__ void ldsm4(uint32_t* r, uint32_t addr) {
    asm volatile("ldmatrix.sync.aligned.m8n8.x4.shared.b16 {%0,%1,%2,%3}, [%4];"
                 : "=r"(r[0]), "=r"(r[1]), "=r"(r[2]), "=r"(r[3]) : "r"(addr));
}
__device__ __forceinline__ void ldsm2(uint32_t* r, uint32_t addr) {
    asm volatile("ldmatrix.sync.aligned.m8n8.x2.shared.b16 {%0,%1}, [%2];"
                 : "=r"(r[0]), "=r"(r[1]) : "r"(addr));
}
__device__ __forceinline__ void mma16816(float* c, const uint32_t* a, const uint32_t* b) {
    asm volatile(
        "mma.sync.aligned.m16n8k16.row.col.f32.bf16.bf16.f32 "
        "{%0,%1,%2,%3}, {%4,%5,%6,%7}, {%8,%9}, {%0,%1,%2,%3};"
        : "+f"(c[0]), "+f"(c[1]), "+f"(c[2]), "+f"(c[3])
        : "r"(a[0]), "r"(a[1]), "r"(a[2]), "r"(a[3]), "r"(b[0]), "r"(b[1]));
}

// ---------------- prep kernels ----------------
__global__ void build_A_kernel(const float* __restrict__ w) {
    int idx = blockIdx.x * blockDim.x + threadIdx.x;
    if (idx >= MROWS * KPAD) return;
    int m = idx / KPAD, k = idx % KPAD;
    int blk = m >> 4, r = m & 15;
    int bin = blk * 8 + (r & 7);
    int src_row = (r >= 8) ? (NFREQ + bin) : bin;
    float v = (k < WIN_LEN) ? w[(size_t)src_row * WIN_LEN + k] : 0.0f;
    __nv_bfloat16 h = __float2bfloat16(v);
    float rem = v - __bfloat162float(h);
    __nv_bfloat16 mm = __float2bfloat16(rem);
    __nv_bfloat16 l = __float2bfloat16(rem - __bfloat162float(mm));
    g_A[0][m][k] = h; g_A[1][m][k] = mm; g_A[2][m][k] = l;
}

__global__ void build_X_kernel(const float* __restrict__ x) {
    int idx = blockIdx.x * blockDim.x + threadIdx.x;
    if (idx >= NBATCH * XSTRIDE) return;
    int b = idx / XSTRIDE, p = idx % XSTRIDE, s = p - PADL;
    float v = (s >= 0 && s < NSAMP) ? x[(size_t)b * NSAMP + s] : 0.0f;
    __nv_bfloat16 h = __float2bfloat16(v);
    float rem = v - __bfloat162float(h);
    __nv_bfloat16 mm = __float2bfloat16(rem);
    __nv_bfloat16 l = __float2bfloat16(rem - __bfloat162float(mm));
    g_X[0][b][p] = h; g_X[1][b][p] = mm; g_X[2][b][p] = l;
}

// Nyquist bin (k = 256), fp32 SIMT — tiny.
__global__ void nyq_kernel(const float* __restrict__ x, const float* __restrict__ w,
                           float* __restrict__ out) {
    int t = blockIdx.x * blockDim.x + threadIdx.x;
    int b = blockIdx.y;
    if (t >= NFRAMES) return;
    const float* wr = w + (size_t)256 * WIN_LEN;
    const float* wi = w + (size_t)513 * WIN_LEN;
    const float* xb = x + (size_t)b * NSAMP;
    int p0 = t * WIN_INC - PADL;
    float r = 0.0f, im = 0.0f;
#pragma unroll 4
    for (int n = 0; n < WIN_LEN; n++) {
        int p = p0 + n;
        float xv = (p >= 0 && p < NSAMP) ? __ldg(xb + p) : 0.0f;
        r  = fmaf(xv, __ldg(wr + n), r);
        im = fmaf(xv, __ldg(wi + n), im);
    }
    float mag = sqrtf(fmaxf(fmaf(r, r, im * im), EPSF));
    float ph  = atan2f(im + EPSF, r + EPSF);
    size_t poff = (size_t)NBATCH * NFREQ * NFRAMES;
    size_t o = ((size_t)b * NFREQ + 256) * NFRAMES + t;
    out[o] = mag;
    out[o + poff] = ph;
}

// ---------------- main MMA kernel ----------------
__global__ void __launch_bounds__(NTHREADS, 2)
stft_mma(float* __restrict__ out) {
    extern __shared__ __align__(128) char smdyn[];
    uint32_t sb = smem_u32(smdyn);
    const int tid = threadIdx.x;
    const int lane = tid & 31, warp = tid >> 5;
    const int mwarp = warp & 3, nwarp = warp >> 2;
    const int mx = blockIdx.x, nt = blockIdx.y, b = blockIdx.z;
    const int m0 = mx * 128, t0 = nt * 128;

    // Persistent load pointers (advance +32 elems per chunk) + smem offsets
    const __nv_bfloat16* pA[2];
    const __nv_bfloat16* pX[4];
    uint32_t offA[2], offX[4];
    {
        const __nv_bfloat16* A0 = &g_A[0][m0][0];
        const __nv_bfloat16* X0 = &g_X[0][b][(size_t)t0 * WIN_INC];
#pragma unroll
        for (int it = 0; it < 2; it++) {
            int op = tid + it * NTHREADS;
            int row = op >> 2, unit = op & 3;
            offA[it] = (uint32_t)(row * 64 + ((unit ^ (row & 3)) << 4));
            pA[it] = A0 + (size_t)row * KPAD + unit * 8;
        }
#pragma unroll
        for (int it = 0; it < 4; it++) {
            int op = tid + it * NTHREADS;
            int row = op >> 3, h8 = op & 7;
            int unit = h8 >> 1, sub = (h8 & 1) << 3;
            offX[it] = (uint32_t)(row * 64 + ((unit ^ (row & 3)) << 4) + sub
                                  + NLVL * TILE_B);
            pX[it] = X0 + (size_t)row * WIN_INC + h8 * 4;
        }
    }

#define LOAD_CHUNK(stage) do {                                            \
    uint32_t _st = sb + (stage) * STAGE_B;                                \
    _Pragma("unroll")                                                     \
    for (int it = 0; it < 2; it++) {                                      \
        uint32_t d = _st + offA[it];                                      \
        cp16(d,              pA[it]);                                     \
        cp16(d + TILE_B,     pA[it] + ALVL);                              \
        cp16(d + 2 * TILE_B, pA[it] + 2 * ALVL);                          \
        pA[it] += 32;                                                     \
    }                                                                     \
    _Pragma("unroll")                                                     \
    for (int it = 0; it < 4; it++) {                                      \
        uint32_t d = _st + offX[it];                                      \
        cp8(d,              pX[it]);                                      \
        cp8(d + TILE_B,     pX[it] + XLVL);                               \
        cp8(d + 2 * TILE_B, pX[it] + 2 * XLVL);                           \
        pX[it] += 32;                                                     \
    }                                                                     \
    asm volatile("cp.async.commit_group;" ::: "memory");                  \
} while (0)

    float c[2][8][4];
#pragma unroll
    for (int im = 0; im < 2; im++)
#pragma unroll
        for (int jn = 0; jn < 8; jn++)
#pragma unroll
            for (int q = 0; q < 4; q++) c[im][jn][q] = 0.0f;

    LOAD_CHUNK(0);

    const int arow0 = mwarp * 32 + (lane & 15);
    const int acol  = lane >> 4;
    const int brow0 = nwarp * 64 + (lane & 7);
    const int bsel  = (lane >> 3) & 1;

    for (int kc = 0; kc < NKCH; kc++) {
        if (kc + 1 < NKCH) {
            LOAD_CHUNK((kc + 1) & 1);
            asm volatile("cp.async.wait_group 1;" ::: "memory");
        } else {
            asm volatile("cp.async.wait_group 0;" ::: "memory");
        }
        __syncthreads();

        uint32_t st = sb + (kc & 1) * STAGE_B;
#pragma unroll
        for (int kh = 0; kh < 2; kh++) {
            uint32_t af[NLVL][2][4];
#pragma unroll
            for (int im = 0; im < 2; im++) {
                int row = arow0 + im * 16;
                uint32_t unit = (uint32_t)(((kh << 1) | acol) ^ (row & 3));
                uint32_t addr = st + row * 64 + (unit << 4);
#pragma unroll
                for (int lvl = 0; lvl < NLVL; lvl++)
                    ldsm4(af[lvl][im], addr + lvl * TILE_B);
            }
#pragma unroll
            for (int jn = 0; jn < 8; jn++) {
                int row = brow0 + jn * 8;
                uint32_t unit = (uint32_t)(((kh << 1) | bsel) ^ (row & 3));
                uint32_t baddr = st + NLVL * TILE_B + row * 64 + (unit << 4);
                uint32_t bf[NLVL][2];
#pragma unroll
                for (int lvl = 0; lvl < NLVL; lvl++)
                    ldsm2(bf[lvl], baddr + lvl * TILE_B);
#pragma unroll
                for (int im = 0; im < 2; im++) {
                    mma16816(c[im][jn], af[0][im], bf[0]);   // h*h
                    mma16816(c[im][jn], af[0][im], bf[1]);   // h*m
                    mma16816(c[im][jn], af[1][im], bf[0]);   // m*h
                    mma16816(c[im][jn], af[0][im], bf[2]);   // h*l
                    mma16816(c[im][jn], af[2][im], bf[0]);   // l*h
                    mma16816(c[im][jn], af[1][im], bf[1]);   // m*m
                }
            }
        }
        __syncthreads();
    }

    // ---- epilogue: (c0,c2) = (real,imag) frame f; (c1,c3) = frame f+1 ----
    const size_t poff = (size_t)NBATCH * NFREQ * NFRAMES;
#pragma unroll
    for (int im = 0; im < 2; im++) {
        int bin = (mx * 8 + mwarp * 2 + im) * 8 + (lane >> 2);
        size_t rowo = ((size_t)b * NFREQ + bin) * NFRAMES;
#pragma unroll
        for (int jn = 0; jn < 8; jn++) {
            int fr = t0 + nwarp * 64 + jn * 8 + ((lane & 3) << 1);
            float r0 = c[im][jn][0], r1 = c[im][jn][1];
            float i0 = c[im][jn][2], i1 = c[im][jn][3];
            if (fr < NFRAMES) {
                out[rowo + fr] = sqrtf(fmaxf(fmaf(r0, r0, i0 * i0), EPSF));
                out[rowo + fr + poff] = atan2f(i0 + EPSF, r0 + EPSF);
            }
            if (fr + 1 < NFRAMES) {
                out[rowo + fr + 1] = sqrtf(fmaxf(fmaf(r1, r1, i1 * i1), EPSF));
                out[rowo + fr + 1 + poff] = atan2f(i1 + EPSF, r1 + EPSF);
            }
        }
    }
}

extern "C" void kernel_launch(void* const* d_in, const int* in_sizes, int n_in,
                              void* d_out, int out_size) {
    const float* x = (const float*)d_in[0];
    const float* w = (const float*)d_in[1];
    if (n_in >= 2 && in_sizes[0] == 2 * NFREQ * WIN_LEN) {
        w = (const float*)d_in[0];
        x = (const float*)d_in[1];
    }
    float* out = (float*)d_out;

    cudaFuncSetAttribute(stft_mma,
                         cudaFuncAttributeMaxDynamicSharedMemorySize, DYN_SMEM);

    build_A_kernel<<<(MROWS * KPAD + 255) / 256, 256>>>(w);
    build_X_kernel<<<(NBATCH * XSTRIDE + 255) / 256, 256>>>(x);
    nyq_kernel<<<dim3(NTILES, NBATCH), 128>>>(x, w, out);
    stft_mma<<<dim3(4, NTILES, NBATCH), NTHREADS, DYN_SMEM>>>(out);
}

// round 12
// speedup vs baseline: 1.1532x; 1.0119x over previous
#include <cuda_runtime.h>
#include <cuda_bf16.h>
#include <math.h>
#include <stdint.h>

#define WIN_LEN 400
#define WIN_INC 100
#define NFREQ   257
#define NBATCH  16
#define NSAMP   160000
#define NFRAMES 1603
#define PADL    300
#define EPSF    1.1920928955078125e-07f

#define KPAD    416             // 13 * 32
#define NKCH    13
#define MROWS   512             // 256 bins x (real, imag)
#define NTILES  13              // ceil(1603/128)
#define XSTRIDE 166848
#define NTHREADS 256

#define TILE_B  8192            // 128 rows x 64 bytes (32 bf16)
#define NLVL    3
#define STAGE_B (2 * NLVL * TILE_B)   // 48 KB
#define NSTAGE  2
#define DYN_SMEM (NSTAGE * STAGE_B)   // 96 KB -> 2 CTAs/SM

// bf16 3-level split: v ~= l0 + l1 + l2 (~24 mantissa bits)
// A row m: block = m/16, r = m%16; bin = block*8 + (r&7); r<8 real, r>=8 imag
__device__ __align__(16) __nv_bfloat16 g_A[NLVL][MROWS][KPAD];
__device__ __align__(16) __nv_bfloat16 g_X[NLVL][NBATCH][XSTRIDE];

#define ALVL ((size_t)MROWS * KPAD)
#define XLVL ((size_t)NBATCH * XSTRIDE)

// ---------------- helpers ----------------
__device__ __forceinline__ uint32_t smem_u32(const void* p) {
    uint32_t a;
    asm("{ .reg .u64 t; cvta.to.shared.u64 t, %1; cvt.u32.u64 %0, t; }"
        : "=r"(a) : "l"(p));
    return a;
}
__device__ __forceinline__ void cp16(uint32_t dst, const void* src) {
    asm volatile("cp.async.cg.shared.global [%0], [%1], 16;"
                 :: "r"(dst), "l"(__cvta_generic_to_global(src)) : "memory");
}
__device__ __forceinline__ void cp8(uint32_t dst, const void* src) {
    asm volatile("cp.async.ca.shared.global [%0], [%1], 8;"
                 :: "r"(dst), "l"(__cvta_generic_to_global(src)) : "memory");
}
__device__ __forceinline__ void ldsm4(uint32_t* r, uint32_t addr) {
    asm volatile("ldmatrix.sync.aligned.m8n8.x4.shared.b16 {%0,%1,%2,%3}, [%4];"
                 : "=r"(r[0]), "=r"(r[1]), "=r"(r[2]), "=r"(r[3]) : "r"(addr));
}
__device__ __forceinline__ void mma16816(float* c, const uint32_t* a, const uint32_t* b) {
    asm volatile(
        "mma.sync.aligned.m16n8k16.row.col.f32.bf16.bf16.f32 "
        "{%0,%1,%2,%3}, {%4,%5,%6,%7}, {%8,%9}, {%0,%1,%2,%3};"
        : "+f"(c[0]), "+f"(c[1]), "+f"(c[2]), "+f"(c[3])
        : "r"(a[0]), "r"(a[1]), "r"(a[2]), "r"(a[3]), "r"(b[0]), "r"(b[1]));
}

// ---------------- prep kernels ----------------
__global__ void build_A_kernel(const float* __restrict__ w) {
    int idx = blockIdx.x * blockDim.x + threadIdx.x;
    if (idx >= MROWS * KPAD) return;
    int m = idx / KPAD, k = idx % KPAD;
    int blk = m >> 4, r = m & 15;
    int bin = blk * 8 + (r & 7);
    int src_row = (r >= 8) ? (NFREQ + bin) : bin;
    float v = (k < WIN_LEN) ? w[(size_t)src_row * WIN_LEN + k] : 0.0f;
    __nv_bfloat16 h = __float2bfloat16(v);
    float rem = v - __bfloat162float(h);
    __nv_bfloat16 mm = __float2bfloat16(rem);
    __nv_bfloat16 l = __float2bfloat16(rem - __bfloat162float(mm));
    g_A[0][m][k] = h; g_A[1][m][k] = mm; g_A[2][m][k] = l;
}

__global__ void build_X_kernel(const float* __restrict__ x) {
    int idx = blockIdx.x * blockDim.x + threadIdx.x;
    if (idx >= NBATCH * XSTRIDE) return;
    int b = idx / XSTRIDE, p = idx % XSTRIDE, s = p - PADL;
    float v = (s >= 0 && s < NSAMP) ? x[(size_t)b * NSAMP + s] : 0.0f;
    __nv_bfloat16 h = __float2bfloat16(v);
    float rem = v - __bfloat162float(h);
    __nv_bfloat16 mm = __float2bfloat16(rem);
    __nv_bfloat16 l = __float2bfloat16(rem - __bfloat162float(mm));
    g_X[0][b][p] = h; g_X[1][b][p] = mm; g_X[2][b][p] = l;
}

// Nyquist bin (k = 256), fp32 SIMT — tiny.
__global__ void nyq_kernel(const float* __restrict__ x, const float* __restrict__ w,
                           float* __restrict__ out) {
    int t = blockIdx.x * blockDim.x + threadIdx.x;
    int b = blockIdx.y;
    if (t >= NFRAMES) return;
    const float* wr = w + (size_t)256 * WIN_LEN;
    const float* wi = w + (size_t)513 * WIN_LEN;
    const float* xb = x + (size_t)b * NSAMP;
    int p0 = t * WIN_INC - PADL;
    float r = 0.0f, im = 0.0f;
#pragma unroll 4
    for (int n = 0; n < WIN_LEN; n++) {
        int p = p0 + n;
        float xv = (p >= 0 && p < NSAMP) ? __ldg(xb + p) : 0.0f;
        r  = fmaf(xv, __ldg(wr + n), r);
        im = fmaf(xv, __ldg(wi + n), im);
    }
    float mag = sqrtf(fmaxf(fmaf(r, r, im * im), EPSF));
    float ph  = atan2f(im + EPSF, r + EPSF);
    size_t poff = (size_t)NBATCH * NFREQ * NFRAMES;
    size_t o = ((size_t)b * NFREQ + 256) * NFRAMES + t;
    out[o] = mag;
    out[o + poff] = ph;
}

// ---------------- main MMA kernel ----------------
__global__ void __launch_bounds__(NTHREADS, 2)
stft_mma(float* __restrict__ out) {
    extern __shared__ __align__(128) char smdyn[];
    uint32_t sb = smem_u32(smdyn);
    const int tid = threadIdx.x;
    const int lane = tid & 31, warp = tid >> 5;
    const int mwarp = warp & 3, nwarp = warp >> 2;
    const int mx = blockIdx.x, nt = blockIdx.y, b = blockIdx.z;
    const int m0 = mx * 128, t0 = nt * 128;

    // Persistent load pointers (advance +32 elems per chunk) + smem offsets
    const __nv_bfloat16* pA[2];
    const __nv_bfloat16* pX[4];
    uint32_t offA[2], offX[4];
    {
        const __nv_bfloat16* A0 = &g_A[0][m0][0];
        const __nv_bfloat16* X0 = &g_X[0][b][(size_t)t0 * WIN_INC];
#pragma unroll
        for (int it = 0; it < 2; it++) {
            int op = tid + it * NTHREADS;
            int row = op >> 2, unit = op & 3;
            offA[it] = (uint32_t)(row * 64 + ((unit ^ (row & 3)) << 4));
            pA[it] = A0 + (size_t)row * KPAD + unit * 8;
        }
#pragma unroll
        for (int it = 0; it < 4; it++) {
            int op = tid + it * NTHREADS;
            int row = op >> 3, h8 = op & 7;
            int unit = h8 >> 1, sub = (h8 & 1) << 3;
            offX[it] = (uint32_t)(row * 64 + ((unit ^ (row & 3)) << 4) + sub
                                  + NLVL * TILE_B);
            pX[it] = X0 + (size_t)row * WIN_INC + h8 * 4;
        }
    }

#define LOAD_CHUNK(stage) do {                                            \
    uint32_t _st = sb + (stage) * STAGE_B;                                \
    _Pragma("unroll")                                                     \
    for (int it = 0; it < 2; it++) {                                      \
        uint32_t d = _st + offA[it];                                      \
        cp16(d,              pA[it]);                                     \
        cp16(d + TILE_B,     pA[it] + ALVL);                              \
        cp16(d + 2 * TILE_B, pA[it] + 2 * ALVL);                          \
        pA[it] += 32;                                                     \
    }                                                                     \
    _Pragma("unroll")                                                     \
    for (int it = 0; it < 4; it++) {                                      \
        uint32_t d = _st + offX[it];                                      \
        cp8(d,              pX[it]);                                      \
        cp8(d + TILE_B,     pX[it] + XLVL);                               \
        cp8(d + 2 * TILE_B, pX[it] + 2 * XLVL);                           \
        pX[it] += 32;                                                     \
    }                                                                     \
    asm volatile("cp.async.commit_group;" ::: "memory");                  \
} while (0)

    float c[2][8][4];
#pragma unroll
    for (int im = 0; im < 2; im++)
#pragma unroll
        for (int jn = 0; jn < 8; jn++)
#pragma unroll
            for (int q = 0; q < 4; q++) c[im][jn][q] = 0.0f;

    LOAD_CHUNK(0);

    // A-fragment addressing (ldmatrix.x4, one m16k16 tile per im per level)
    const int arow0 = mwarp * 32 + (lane & 15);
    const int acol  = lane >> 4;
    // B-fragment addressing (ldmatrix.x4, TWO n8 blocks x both k-halves):
    //   lanes 0-7  -> matrix0: n-block jg*2,   k 0-7
    //   lanes 8-15 -> matrix1: n-block jg*2,   k 8-15
    //   lanes 16-23-> matrix2: n-block jg*2+1, k 0-7
    //   lanes 24-31-> matrix3: n-block jg*2+1, k 8-15
    const int brow0 = nwarp * 64 + ((lane >> 4) << 3) + (lane & 7);
    const int bksel = (lane >> 3) & 1;

    for (int kc = 0; kc < NKCH; kc++) {
        if (kc + 1 < NKCH) {
            LOAD_CHUNK((kc + 1) & 1);
            asm volatile("cp.async.wait_group 1;" ::: "memory");
        } else {
            asm volatile("cp.async.wait_group 0;" ::: "memory");
        }
        __syncthreads();

        uint32_t st = sb + (kc & 1) * STAGE_B;
#pragma unroll
        for (int kh = 0; kh < 2; kh++) {
            uint32_t af[NLVL][2][4];
#pragma unroll
            for (int im = 0; im < 2; im++) {
                int row = arow0 + im * 16;
                uint32_t unit = (uint32_t)(((kh << 1) | acol) ^ (row & 3));
                uint32_t addr = st + row * 64 + (unit << 4);
#pragma unroll
                for (int lvl = 0; lvl < NLVL; lvl++)
                    ldsm4(af[lvl][im], addr + lvl * TILE_B);
            }
#pragma unroll
            for (int jg = 0; jg < 4; jg++) {
                int row = brow0 + jg * 16;
                uint32_t unit = (uint32_t)(((kh << 1) | bksel) ^ (row & 3));
                uint32_t baddr = st + NLVL * TILE_B + row * 64 + (unit << 4);
                uint32_t bf[NLVL][4];
#pragma unroll
                for (int lvl = 0; lvl < NLVL; lvl++)
                    ldsm4(bf[lvl], baddr + lvl * TILE_B);
#pragma unroll
                for (int im = 0; im < 2; im++) {
#pragma unroll
                    for (int j2 = 0; j2 < 2; j2++) {
                        float* cc = c[im][jg * 2 + j2];
                        mma16816(cc, af[0][im], &bf[0][2 * j2]);   // h*h
                        mma16816(cc, af[0][im], &bf[1][2 * j2]);   // h*m
                        mma16816(cc, af[1][im], &bf[0][2 * j2]);   // m*h
                        mma16816(cc, af[0][im], &bf[2][2 * j2]);   // h*l
                        mma16816(cc, af[2][im], &bf[0][2 * j2]);   // l*h
                        mma16816(cc, af[1][im], &bf[1][2 * j2]);   // m*m
                    }
                }
            }
        }
        __syncthreads();
    }

    // ---- epilogue: (c0,c2) = (real,imag) frame f; (c1,c3) = frame f+1 ----
    const size_t poff = (size_t)NBATCH * NFREQ * NFRAMES;
#pragma unroll
    for (int im = 0; im < 2; im++) {
        int bin = (mx * 8 + mwarp * 2 + im) * 8 + (lane >> 2);
        size_t rowo = ((size_t)b * NFREQ + bin) * NFRAMES;
#pragma unroll
        for (int jn = 0; jn < 8; jn++) {
            int fr = t0 + nwarp * 64 + jn * 8 + ((lane & 3) << 1);
            float r0 = c[im][jn][0], r1 = c[im][jn][1];
            float i0 = c[im][jn][2], i1 = c[im][jn][3];
            if (fr < NFRAMES) {
                out[rowo + fr] = sqrtf(fmaxf(fmaf(r0, r0, i0 * i0), EPSF));
                out[rowo + fr + poff] = atan2f(i0 + EPSF, r0 + EPSF);
            }
            if (fr + 1 < NFRAMES) {
                out[rowo + fr + 1] = sqrtf(fmaxf(fmaf(r1, r1, i1 * i1), EPSF));
                out[rowo + fr + 1 + poff] = atan2f(i1 + EPSF, r1 + EPSF);
            }
        }
    }
}

extern "C" void kernel_launch(void* const* d_in, const int* in_sizes, int n_in,
                              void* d_out, int out_size) {
    const float* x = (const float*)d_in[0];
    const float* w = (const float*)d_in[1];
    if (n_in >= 2 && in_sizes[0] == 2 * NFREQ * WIN_LEN) {
        w = (const float*)d_in[0];
        x = (const float*)d_in[1];
    }
    float* out = (float*)d_out;

    cudaFuncSetAttribute(stft_mma,
                         cudaFuncAttributeMaxDynamicSharedMemorySize, DYN_SMEM);

    build_A_kernel<<<(MROWS * KPAD + 255) / 256, 256>>>(w);
    build_X_kernel<<<(NBATCH * XSTRIDE + 255) / 256, 256>>>(x);
    nyq_kernel<<<dim3(NTILES, NBATCH), 128>>>(x, w, out);
    stft_mma<<<dim3(4, NTILES, NBATCH), NTHREADS, DYN_SMEM>>>(out);
}

// round 15
// speedup vs baseline: 1.4383x; 1.2472x over previous
#include <cuda_runtime.h>
#include <cuda_bf16.h>
#include <math.h>
#include <stdint.h>

#define WIN_LEN 400
#define WIN_INC 100
#define NFREQ   257
#define NBATCH  16
#define NSAMP   160000
#define NFRAMES 1603
#define PADL    300
#define EPSF    1.1920928955078125e-07f

#define KK      224             // padded K per E/O branch (200 real)
#define NKC     7               // K chunks of 32
#define MROWS   512             // 128 bins x 4 types (Er,Ei,Or',Oi')
#define NTILES  13              // ceil(1603/128)
#define XESTRIDE 83456
#define NTHREADS 256

#define TILE_B  8192            // 128 rows x 64 bytes (32 bf16)
#define NLVL    3
#define STAGE_B (9 * TILE_B)    // A x3lvl, BE x3lvl, BO x3lvl = 72 KB
#define NSTAGE  2
#define DYN_SMEM (NSTAGE * STAGE_B)   // 144 KB -> 1 CTA/SM

__device__ __align__(16) __nv_bfloat16 g_A[NLVL][MROWS][KK];
__device__ __align__(16) __nv_bfloat16 g_XE[NLVL][NBATCH][XESTRIDE];
__device__ __align__(16) __nv_bfloat16 g_XO[NLVL][NBATCH][XESTRIDE];

#define ALVL ((size_t)MROWS * KK)
#define XLVL ((size_t)NBATCH * XESTRIDE)

// ---------------- helpers ----------------
__device__ __forceinline__ uint32_t smem_u32(const void* p) {
    uint32_t a;
    asm("{ .reg .u64 t; cvta.to.shared.u64 t, %1; cvt.u32.u64 %0, t; }"
        : "=r"(a) : "l"(p));
    return a;
}
__device__ __forceinline__ void cp16(uint32_t dst, const void* src) {
    asm volatile("cp.async.cg.shared.global [%0], [%1], 16;"
                 :: "r"(dst), "l"(__cvta_generic_to_global(src)) : "memory");
}
__device__ __forceinline__ void cp4(uint32_t dst, const void* src) {
    asm volatile("cp.async.ca.shared.global [%0], [%1], 4;"
                 :: "r"(dst), "l"(__cvta_generic_to_global(src)) : "memory");
}
__device__ __forceinline__ void ldsm4(uint32_t* r, uint32_t addr) {
    asm volatile("ldmatrix.sync.aligned.m8n8.x4.shared.b16 {%0,%1,%2,%3}, [%4];"
                 : "=r"(r[0]), "=r"(r[1]), "=r"(r[2]), "=r"(r[3]) : "r"(addr));
}
__device__ __forceinline__ void mma16816(float* c, const uint32_t* a, const uint32_t* b) {
    asm volatile(
        "mma.sync.aligned.m16n8k16.row.col.f32.bf16.bf16.f32 "
        "{%0,%1,%2,%3}, {%4,%5,%6,%7}, {%8,%9}, {%0,%1,%2,%3};"
        : "+f"(c[0]), "+f"(c[1]), "+f"(c[2]), "+f"(c[3])
        : "r"(a[0]), "r"(a[1]), "r"(a[2]), "r"(a[3]), "r"(b[0]), "r"(b[1]));
}
__device__ __forceinline__ void split3f(float v, __nv_bfloat16* h,
                                        __nv_bfloat16* m, __nv_bfloat16* l) {
    __nv_bfloat16 a = __float2bfloat16(v);
    float r1 = v - __bfloat162float(a);
    __nv_bfloat16 bb = __float2bfloat16(r1);
    *h = a; *m = bb; *l = __float2bfloat16(r1 - __bfloat162float(bb));
}

// ---------------- prep kernels ----------------
// A row m: mx=m>>7; sub=m&127: mwarp=sub>>5, s2=sub&31; type=s2>>3
// (0 Er, 1 Ei, 2 Or', 3 Oi'); bin j = mx*32 + mwarp*8 + (s2&7).
// Basis = PROVIDED fp32 weight: E at even samples, O' (twiddle-absorbed) at odd.
__global__ void build_A_kernel(const float* __restrict__ w) {
    int idx = blockIdx.x * blockDim.x + threadIdx.x;
    if (idx >= MROWS * KK) return;
    int m = idx / KK, mk = idx % KK;
    int mx = m >> 7, sub = m & 127;
    int mwarp = sub >> 5, s2 = sub & 31;
    int type = s2 >> 3;
    int bin = mx * 32 + mwarp * 8 + (s2 & 7);
    float v = 0.0f;
    if (mk < 200) {
        int n = ((type & 2) ? (2 * mk + 1) : (2 * mk));      // E even / O' odd
        int row = (type & 1) ? (NFREQ + bin) : bin;          // real / imag rows
        v = w[(size_t)row * WIN_LEN + n];
    }
    __nv_bfloat16 h, mm, l;
    split3f(v, &h, &mm, &l);
    g_A[0][m][mk] = h; g_A[1][m][mk] = mm; g_A[2][m][mk] = l;
}

// Decimated padded signals: xe[q] = xpad[2q], xo[q] = xpad[2q+1]; xpad[p]=x[p-300]
__global__ void build_XEO_kernel(const float* __restrict__ x) {
    int idx = blockIdx.x * blockDim.x + threadIdx.x;
    if (idx >= NBATCH * XESTRIDE) return;
    int b = idx / XESTRIDE, q = idx % XESTRIDE;
    const float* xb = x + (size_t)b * NSAMP;
    int se = 2 * q - PADL, so = se + 1;
    float ve = (se >= 0 && se < NSAMP) ? xb[se] : 0.0f;
    float vo = (so >= 0 && so < NSAMP) ? xb[so] : 0.0f;
    __nv_bfloat16 h, mm, l;
    split3f(ve, &h, &mm, &l);
    g_XE[0][b][q] = h; g_XE[1][b][q] = mm; g_XE[2][b][q] = l;
    split3f(vo, &h, &mm, &l);
    g_XO[0][b][q] = h; g_XO[1][b][q] = mm; g_XO[2][b][q] = l;
}

// Bin k=128 via the provided weight rows (128 real, 385 imag). Warp per frame.
__global__ void k128_kernel(const float* __restrict__ x, const float* __restrict__ w,
                            float* __restrict__ out) {
    int wid = threadIdx.x >> 5, lane = threadIdx.x & 31;
    int t = blockIdx.x * 8 + wid;
    int b = blockIdx.y;
    if (t >= NFRAMES) return;
    const float* wr = w + (size_t)128 * WIN_LEN;
    const float* wi = w + (size_t)(NFREQ + 128) * WIN_LEN;
    const float* xb = x + (size_t)b * NSAMP;
    int p0 = t * WIN_INC - PADL;
    float accr = 0.0f, acci = 0.0f;
    for (int n = lane; n < WIN_LEN; n += 32) {
        int p = p0 + n;
        float xv = (p >= 0 && p < NSAMP) ? xb[p] : 0.0f;
        accr = fmaf(xv, __ldg(wr + n), accr);
        acci = fmaf(xv, __ldg(wi + n), acci);
    }
#pragma unroll
    for (int o = 16; o > 0; o >>= 1) {
        accr += __shfl_down_sync(0xFFFFFFFFu, accr, o);
        acci += __shfl_down_sync(0xFFFFFFFFu, acci, o);
    }
    if (lane == 0) {
        float mag = sqrtf(fmaxf(fmaf(accr, accr, acci * acci), EPSF));
        float ph  = atan2f(acci + EPSF, accr + EPSF);
        size_t poff = (size_t)NBATCH * NFREQ * NFRAMES;
        size_t o = ((size_t)b * NFREQ + 128) * NFRAMES + t;
        out[o] = mag;
        out[o + poff] = ph;
    }
}

// ---------------- main MMA kernel ----------------
__global__ void __launch_bounds__(NTHREADS)
stft_mma(float* __restrict__ out) {
    extern __shared__ __align__(128) char smdyn[];
    uint32_t sb = smem_u32(smdyn);
    const int tid = threadIdx.x;
    const int lane = tid & 31, warp = tid >> 5;
    const int mwarp = warp & 3, nwarp = warp >> 2;
    const int mx = blockIdx.x, nt = blockIdx.y, b = blockIdx.z;
    const int m0 = mx * 128, t0 = nt * 128;

    uint32_t offA[2]; size_t srcA[2];
    uint32_t offB[8]; size_t srcB[8];
    {
#pragma unroll
        for (int it = 0; it < 2; it++) {
            int op = tid + it * NTHREADS;
            int row = op >> 2, u4 = op & 3;
            offA[it] = (uint32_t)(row * 64 + ((u4 ^ (row & 3)) << 4));
            srcA[it] = (size_t)(m0 + row) * KK + u4 * 8;
        }
#pragma unroll
        for (int it = 0; it < 8; it++) {
            int op = tid + it * NTHREADS;
            int row = op >> 4, seg = op & 15;
            int uB = seg >> 2, subB = (seg & 3) << 2;
            offB[it] = (uint32_t)(row * 64 + ((uB ^ (row & 3)) << 4) + subB);
            srcB[it] = (size_t)(t0 + row) * 50 + seg * 2;
        }
    }
    const __nv_bfloat16* AE = &g_A[0][0][0];
    const __nv_bfloat16* XE = &g_XE[0][b][0];
    const __nv_bfloat16* XO = &g_XO[0][b][0];

#define LOAD_CHUNK(stage, kc) do {                                        \
    uint32_t _st = sb + (stage) * STAGE_B;                                \
    int _k0 = (kc) * 32;                                                  \
    _Pragma("unroll")                                                     \
    for (int it = 0; it < 2; it++) {                                      \
        uint32_t d = _st + offA[it];                                      \
        const __nv_bfloat16* s = AE + srcA[it] + _k0;                     \
        cp16(d,              s);                                          \
        cp16(d + TILE_B,     s + ALVL);                                   \
        cp16(d + 2 * TILE_B, s + 2 * ALVL);                               \
    }                                                                     \
    _Pragma("unroll")                                                     \
    for (int it = 0; it < 8; it++) {                                      \
        uint32_t d = _st + 3 * TILE_B + offB[it];                         \
        size_t so = srcB[it] + _k0;                                       \
        cp4(d,              XE + so);                                     \
        cp4(d + TILE_B,     XE + so + XLVL);                              \
        cp4(d + 2 * TILE_B, XE + so + 2 * XLVL);                          \
        cp4(d + 3 * TILE_B, XO + so);                                     \
        cp4(d + 4 * TILE_B, XO + so + XLVL);                              \
        cp4(d + 5 * TILE_B, XO + so + 2 * XLVL);                          \
    }                                                                     \
    asm volatile("cp.async.commit_group;" ::: "memory");                  \
} while (0)

    float c[2][8][4];
#pragma unroll
    for (int im = 0; im < 2; im++)
#pragma unroll
        for (int jn = 0; jn < 8; jn++)
#pragma unroll
            for (int q = 0; q < 4; q++) c[im][jn][q] = 0.0f;

    LOAD_CHUNK(0, 0);

    const int arow0 = mwarp * 32 + (lane & 15);   // E rows; O at +16
    const int acol  = lane >> 4;
    const int brow0 = nwarp * 64 + ((lane >> 4) << 3) + (lane & 7);
    const int bksel = (lane >> 3) & 1;

    for (int kc = 0; kc < NKC; kc++) {
        if (kc + 1 < NKC) {
            LOAD_CHUNK((kc + 1) & 1, kc + 1);
            asm volatile("cp.async.wait_group 1;" ::: "memory");
        } else {
            asm volatile("cp.async.wait_group 0;" ::: "memory");
        }
        __syncthreads();

        uint32_t st = sb + (kc & 1) * STAGE_B;
        const int khmax = (kc == NKC - 1) ? 1 : 2;   // real K = 208 of 224
#pragma unroll
        for (int kh = 0; kh < 2; kh++) {
            if (kh >= khmax) break;
            uint32_t af[NLVL][2][4];
#pragma unroll
            for (int im = 0; im < 2; im++) {
                int row = arow0 + im * 16;
                uint32_t unit = (uint32_t)(((kh << 1) | acol) ^ (row & 3));
                uint32_t addr = st + row * 64 + (unit << 4);
#pragma unroll
                for (int lvl = 0; lvl < NLVL; lvl++)
                    ldsm4(af[lvl][im], addr + lvl * TILE_B);
            }
#pragma unroll
            for (int jp = 0; jp < 4; jp++) {
                int row = brow0 + jp * 16;
                uint32_t unit = (uint32_t)(((kh << 1) | bksel) ^ (row & 3));
                uint32_t be = st + 3 * TILE_B + row * 64 + (unit << 4);
                uint32_t bfE[NLVL][4], bfO[NLVL][4];
#pragma unroll
                for (int lvl = 0; lvl < NLVL; lvl++) {
                    ldsm4(bfE[lvl], be + lvl * TILE_B);
                    ldsm4(bfO[lvl], be + (3 + lvl) * TILE_B);
                }
#pragma unroll
                for (int j2 = 0; j2 < 2; j2++) {
                    float* cE = c[0][jp * 2 + j2];
                    float* cO = c[1][jp * 2 + j2];
                    mma16816(cE, af[0][0], &bfE[0][2 * j2]);   // h*h
                    mma16816(cE, af[0][0], &bfE[1][2 * j2]);   // h*m
                    mma16816(cE, af[1][0], &bfE[0][2 * j2]);   // m*h
                    mma16816(cE, af[0][0], &bfE[2][2 * j2]);   // h*l
                    mma16816(cE, af[2][0], &bfE[0][2 * j2]);   // l*h
                    mma16816(cE, af[1][0], &bfE[1][2 * j2]);   // m*m
                    mma16816(cO, af[0][1], &bfO[0][2 * j2]);
                    mma16816(cO, af[0][1], &bfO[1][2 * j2]);
                    mma16816(cO, af[1][1], &bfO[0][2 * j2]);
                    mma16816(cO, af[0][1], &bfO[2][2 * j2]);
                    mma16816(cO, af[2][1], &bfO[0][2 * j2]);
                    mma16816(cO, af[1][1], &bfO[1][2 * j2]);
                }
            }
        }
        __syncthreads();
    }

    // ---- combine (twiddle absorbed in O'): X_j = E + O', X_{256-j} = conj(E - O')
    const size_t poff = (size_t)NBATCH * NFREQ * NFRAMES;
    const int k = mx * 32 + mwarp * 8 + (lane >> 2);      // 0..127
    size_t rowK = ((size_t)b * NFREQ + k) * NFRAMES;
    size_t rowC = ((size_t)b * NFREQ + (256 - k)) * NFRAMES;
#pragma unroll
    for (int jn = 0; jn < 8; jn++) {
        int fr = t0 + nwarp * 64 + jn * 8 + ((lane & 3) << 1);
#pragma unroll
        for (int h = 0; h < 2; h++) {
            int f = fr + h;
            if (f >= NFRAMES) continue;
            float er = c[0][jn][0 + h], ei = c[0][jn][2 + h];
            float orr = c[1][jn][0 + h], oi = c[1][jn][2 + h];
            float xr = er + orr, xi = ei + oi;
            out[rowK + f] = sqrtf(fmaxf(fmaf(xr, xr, xi * xi), EPSF));
            out[rowK + f + poff] = atan2f(xi + EPSF, xr + EPSF);
            float yr = er - orr, yi = oi - ei;
            out[rowC + f] = sqrtf(fmaxf(fmaf(yr, yr, yi * yi), EPSF));
            out[rowC + f + poff] = atan2f(yi + EPSF, yr + EPSF);
        }
    }
}

extern "C" void kernel_launch(void* const* d_in, const int* in_sizes, int n_in,
                              void* d_out, int out_size) {
    const float* x = (const float*)d_in[0];
    const float* w = (const float*)d_in[1];
    if (n_in >= 2 && in_sizes[0] == 2 * NFREQ * WIN_LEN) {
        w = (const float*)d_in[0];
        x = (const float*)d_in[1];
    }
    float* out = (float*)d_out;

    cudaFuncSetAttribute(stft_mma,
                         cudaFuncAttributeMaxDynamicSharedMemorySize, DYN_SMEM);

    build_A_kernel<<<(MROWS * KK + 255) / 256, 256>>>(w);
    build_XEO_kernel<<<(NBATCH * XESTRIDE + 255) / 256, 256>>>(x);
    k128_kernel<<<dim3((NFRAMES + 7) / 8, NBATCH), 256>>>(x, w, out);
    stft_mma<<<dim3(4, NTILES, NBATCH), NTHREADS, DYN_SMEM>>>(out);
}

// round 16
// speedup vs baseline: 1.6889x; 1.1743x over previous
#include <cuda_runtime.h>
#include <cuda_bf16.h>
#include <math.h>
#include <stdint.h>

#define WIN_LEN 400
#define WIN_INC 100
#define NFREQ   257
#define NBATCH  16
#define NSAMP   160000
#define NFRAMES 1603
#define PADL    300
#define EPSF    1.1920928955078125e-07f

#define KK      224             // padded K per E/O branch (208 real = 13*16)
#define NKC     13              // K chunks of 16
#define MROWS   512             // 128 bins x 4 types (Er,Ei,Or',Oi')
#define NTILES  13              // ceil(1603/128)
#define XESTRIDE 83456
#define NTHREADS 256

#define TILE_B  4096            // 128 rows x 32 bytes (16 bf16)
#define NLVL    3
#define STAGE_B (9 * TILE_B)    // A x3lvl, BE x3lvl, BO x3lvl = 36 KB
#define NSTAGE  2
#define DYN_SMEM (NSTAGE * STAGE_B)   // 72 KB -> 2 CTAs/SM

__device__ __align__(16) __nv_bfloat16 g_A[NLVL][MROWS][KK];
__device__ __align__(16) __nv_bfloat16 g_XE[NLVL][NBATCH][XESTRIDE];
__device__ __align__(16) __nv_bfloat16 g_XO[NLVL][NBATCH][XESTRIDE];

#define ALVL ((size_t)MROWS * KK)
#define XLVL ((size_t)NBATCH * XESTRIDE)

// 32B-row swizzle: unit ^= (row>>2)&1  -> 8-row ldmatrix phases hit
// bank groups {0,2,4,6,1,3,5,7}: conflict-free.
#define SWZ32(row, unit) ((uint32_t)((row) * 32 + (((unit) ^ (((row) >> 2) & 1)) << 4)))

// ---------------- helpers ----------------
__device__ __forceinline__ uint32_t smem_u32(const void* p) {
    uint32_t a;
    asm("{ .reg .u64 t; cvta.to.shared.u64 t, %1; cvt.u32.u64 %0, t; }"
        : "=r"(a) : "l"(p));
    return a;
}
__device__ __forceinline__ void cp16(uint32_t dst, const void* src) {
    asm volatile("cp.async.cg.shared.global [%0], [%1], 16;"
                 :: "r"(dst), "l"(__cvta_generic_to_global(src)) : "memory");
}
__device__ __forceinline__ void cp4(uint32_t dst, const void* src) {
    asm volatile("cp.async.ca.shared.global [%0], [%1], 4;"
                 :: "r"(dst), "l"(__cvta_generic_to_global(src)) : "memory");
}
__device__ __forceinline__ void ldsm4(uint32_t* r, uint32_t addr) {
    asm volatile("ldmatrix.sync.aligned.m8n8.x4.shared.b16 {%0,%1,%2,%3}, [%4];"
                 : "=r"(r[0]), "=r"(r[1]), "=r"(r[2]), "=r"(r[3]) : "r"(addr));
}
__device__ __forceinline__ void mma16816(float* c, const uint32_t* a, const uint32_t* b) {
    asm volatile(
        "mma.sync.aligned.m16n8k16.row.col.f32.bf16.bf16.f32 "
        "{%0,%1,%2,%3}, {%4,%5,%6,%7}, {%8,%9}, {%0,%1,%2,%3};"
        : "+f"(c[0]), "+f"(c[1]), "+f"(c[2]), "+f"(c[3])
        : "r"(a[0]), "r"(a[1]), "r"(a[2]), "r"(a[3]), "r"(b[0]), "r"(b[1]));
}
__device__ __forceinline__ void split3f(float v, __nv_bfloat16* h,
                                        __nv_bfloat16* m, __nv_bfloat16* l) {
    __nv_bfloat16 a = __float2bfloat16(v);
    float r1 = v - __bfloat162float(a);
    __nv_bfloat16 bb = __float2bfloat16(r1);
    *h = a; *m = bb; *l = __float2bfloat16(r1 - __bfloat162float(bb));
}

// ---------------- prep kernels ----------------
// A row m: mx=m>>7; sub=m&127: mwarp=sub>>5, s2=sub&31; type=s2>>3
// (0 Er, 1 Ei, 2 Or', 3 Oi'); bin j = mx*32 + mwarp*8 + (s2&7).
// Basis = PROVIDED fp32 weight: E at even samples, O' (twiddle-absorbed) at odd.
__global__ void build_A_kernel(const float* __restrict__ w) {
    int idx = blockIdx.x * blockDim.x + threadIdx.x;
    if (idx >= MROWS * KK) return;
    int m = idx / KK, mk = idx % KK;
    int mx = m >> 7, sub = m & 127;
    int mwarp = sub >> 5, s2 = sub & 31;
    int type = s2 >> 3;
    int bin = mx * 32 + mwarp * 8 + (s2 & 7);
    float v = 0.0f;
    if (mk < 200) {
        int n = ((type & 2) ? (2 * mk + 1) : (2 * mk));      // E even / O' odd
        int row = (type & 1) ? (NFREQ + bin) : bin;          // real / imag rows
        v = w[(size_t)row * WIN_LEN + n];
    }
    __nv_bfloat16 h, mm, l;
    split3f(v, &h, &mm, &l);
    g_A[0][m][mk] = h; g_A[1][m][mk] = mm; g_A[2][m][mk] = l;
}

// Decimated padded signals: xe[q] = xpad[2q], xo[q] = xpad[2q+1]; xpad[p]=x[p-300]
__global__ void build_XEO_kernel(const float* __restrict__ x) {
    int idx = blockIdx.x * blockDim.x + threadIdx.x;
    if (idx >= NBATCH * XESTRIDE) return;
    int b = idx / XESTRIDE, q = idx % XESTRIDE;
    const float* xb = x + (size_t)b * NSAMP;
    int se = 2 * q - PADL, so = se + 1;
    float ve = (se >= 0 && se < NSAMP) ? xb[se] : 0.0f;
    float vo = (so >= 0 && so < NSAMP) ? xb[so] : 0.0f;
    __nv_bfloat16 h, mm, l;
    split3f(ve, &h, &mm, &l);
    g_XE[0][b][q] = h; g_XE[1][b][q] = mm; g_XE[2][b][q] = l;
    split3f(vo, &h, &mm, &l);
    g_XO[0][b][q] = h; g_XO[1][b][q] = mm; g_XO[2][b][q] = l;
}

// Bin k=128 via the provided weight rows (128 real, 385 imag). Warp per frame.
__global__ void k128_kernel(const float* __restrict__ x, const float* __restrict__ w,
                            float* __restrict__ out) {
    int wid = threadIdx.x >> 5, lane = threadIdx.x & 31;
    int t = blockIdx.x * 8 + wid;
    int b = blockIdx.y;
    if (t >= NFRAMES) return;
    const float* wr = w + (size_t)128 * WIN_LEN;
    const float* wi = w + (size_t)(NFREQ + 128) * WIN_LEN;
    const float* xb = x + (size_t)b * NSAMP;
    int p0 = t * WIN_INC - PADL;
    float accr = 0.0f, acci = 0.0f;
    for (int n = lane; n < WIN_LEN; n += 32) {
        int p = p0 + n;
        float xv = (p >= 0 && p < NSAMP) ? xb[p] : 0.0f;
        accr = fmaf(xv, __ldg(wr + n), accr);
        acci = fmaf(xv, __ldg(wi + n), acci);
    }
#pragma unroll
    for (int o = 16; o > 0; o >>= 1) {
        accr += __shfl_down_sync(0xFFFFFFFFu, accr, o);
        acci += __shfl_down_sync(0xFFFFFFFFu, acci, o);
    }
    if (lane == 0) {
        float mag = sqrtf(fmaxf(fmaf(accr, accr, acci * acci), EPSF));
        float ph  = atan2f(acci + EPSF, accr + EPSF);
        size_t poff = (size_t)NBATCH * NFREQ * NFRAMES;
        size_t o = ((size_t)b * NFREQ + 128) * NFRAMES + t;
        out[o] = mag;
        out[o + poff] = ph;
    }
}

// ---------------- main MMA kernel ----------------
__global__ void __launch_bounds__(NTHREADS, 2)
stft_mma(float* __restrict__ out) {
    extern __shared__ __align__(128) char smdyn[];
    uint32_t sb = smem_u32(smdyn);
    const int tid = threadIdx.x;
    const int lane = tid & 31, warp = tid >> 5;
    const int mwarp = warp & 3, nwarp = warp >> 2;
    const int mx = blockIdx.x, nt = blockIdx.y, b = blockIdx.z;
    const int m0 = mx * 128, t0 = nt * 128;

    // Loader addressing.
    // A: 256 granules (1 cp16/thread/level): row = tid>>1, unit = tid&1
    uint32_t offA; size_t srcA;
    {
        int row = tid >> 1, u = tid & 1;
        offA = SWZ32(row, u);
        srcA = (size_t)(m0 + row) * KK + u * 8;
    }
    // B: 1024 granules (4 cp4/thread/level/EO): row = op>>3, g = op&7 (4B granule)
    uint32_t offB[4]; size_t srcB[4];
#pragma unroll
    for (int it = 0; it < 4; it++) {
        int op = tid + it * NTHREADS;
        int row = op >> 3, g = op & 7;
        offB[it] = SWZ32(row, g >> 2) + ((g & 3) << 2);
        srcB[it] = (size_t)(t0 + row) * 50 + g * 2;
    }
    const __nv_bfloat16* AE = &g_A[0][0][0];
    const __nv_bfloat16* XE = &g_XE[0][b][0];
    const __nv_bfloat16* XO = &g_XO[0][b][0];

#define LOAD_CHUNK(stage, kc) do {                                        \
    uint32_t _st = sb + (stage) * STAGE_B;                                \
    int _k0 = (kc) * 16;                                                  \
    {                                                                     \
        uint32_t d = _st + offA;                                          \
        const __nv_bfloat16* s = AE + srcA + _k0;                         \
        cp16(d,              s);                                          \
        cp16(d + TILE_B,     s + ALVL);                                   \
        cp16(d + 2 * TILE_B, s + 2 * ALVL);                               \
    }                                                                     \
    _Pragma("unroll")                                                     \
    for (int it = 0; it < 4; it++) {                                      \
        uint32_t d = _st + 3 * TILE_B + offB[it];                         \
        size_t so = srcB[it] + _k0;                                       \
        cp4(d,              XE + so);                                     \
        cp4(d + TILE_B,     XE + so + XLVL);                              \
        cp4(d + 2 * TILE_B, XE + so + 2 * XLVL);                          \
        cp4(d + 3 * TILE_B, XO + so);                                     \
        cp4(d + 4 * TILE_B, XO + so + XLVL);                              \
        cp4(d + 5 * TILE_B, XO + so + 2 * XLVL);                          \
    }                                                                     \
    asm volatile("cp.async.commit_group;" ::: "memory");                  \
} while (0)

    float c[2][8][4];
#pragma unroll
    for (int im = 0; im < 2; im++)
#pragma unroll
        for (int jn = 0; jn < 8; jn++)
#pragma unroll
            for (int q = 0; q < 4; q++) c[im][jn][q] = 0.0f;

    LOAD_CHUNK(0, 0);

    const int arow0 = mwarp * 32 + (lane & 15);   // E rows; O at +16
    const int acol  = lane >> 4;                  // k-half selector
    const int brow0 = nwarp * 64 + ((lane >> 4) << 3) + (lane & 7);
    const int bksel = (lane >> 3) & 1;

    for (int kc = 0; kc < NKC; kc++) {
        if (kc + 1 < NKC) {
            LOAD_CHUNK((kc + 1) & 1, kc + 1);
            asm volatile("cp.async.wait_group 1;" ::: "memory");
        } else {
            asm volatile("cp.async.wait_group 0;" ::: "memory");
        }
        __syncthreads();

        uint32_t st = sb + (kc & 1) * STAGE_B;
        uint32_t af[NLVL][2][4];
#pragma unroll
        for (int im = 0; im < 2; im++) {
            int row = arow0 + im * 16;
            uint32_t addr = st + SWZ32(row, acol);
#pragma unroll
            for (int lvl = 0; lvl < NLVL; lvl++)
                ldsm4(af[lvl][im], addr + lvl * TILE_B);
        }
#pragma unroll
        for (int jp = 0; jp < 4; jp++) {
            int row = brow0 + jp * 16;
            uint32_t be = st + 3 * TILE_B + SWZ32(row, bksel);
            uint32_t bfE[NLVL][4], bfO[NLVL][4];
#pragma unroll
            for (int lvl = 0; lvl < NLVL; lvl++) {
                ldsm4(bfE[lvl], be + lvl * TILE_B);
                ldsm4(bfO[lvl], be + (3 + lvl) * TILE_B);
            }
#pragma unroll
            for (int j2 = 0; j2 < 2; j2++) {
                float* cE = c[0][jp * 2 + j2];
                float* cO = c[1][jp * 2 + j2];
                mma16816(cE, af[0][0], &bfE[0][2 * j2]);   // h*h
                mma16816(cE, af[0][0], &bfE[1][2 * j2]);   // h*m
                mma16816(cE, af[1][0], &bfE[0][2 * j2]);   // m*h
                mma16816(cE, af[0][0], &bfE[2][2 * j2]);   // h*l
                mma16816(cE, af[2][0], &bfE[0][2 * j2]);   // l*h
                mma16816(cE, af[1][0], &bfE[1][2 * j2]);   // m*m
                mma16816(cO, af[0][1], &bfO[0][2 * j2]);
                mma16816(cO, af[0][1], &bfO[1][2 * j2]);
                mma16816(cO, af[1][1], &bfO[0][2 * j2]);
                mma16816(cO, af[0][1], &bfO[2][2 * j2]);
                mma16816(cO, af[2][1], &bfO[0][2 * j2]);
                mma16816(cO, af[1][1], &bfO[1][2 * j2]);
            }
        }
        __syncthreads();
    }

    // ---- combine (twiddle absorbed in O'): X_j = E + O', X_{256-j} = conj(E - O')
    const size_t poff = (size_t)NBATCH * NFREQ * NFRAMES;
    const int k = mx * 32 + mwarp * 8 + (lane >> 2);      // 0..127
    size_t rowK = ((size_t)b * NFREQ + k) * NFRAMES;
    size_t rowC = ((size_t)b * NFREQ + (256 - k)) * NFRAMES;
#pragma unroll
    for (int jn = 0; jn < 8; jn++) {
        int fr = t0 + nwarp * 64 + jn * 8 + ((lane & 3) << 1);
#pragma unroll
        for (int h = 0; h < 2; h++) {
            int f = fr + h;
            if (f >= NFRAMES) continue;
            float er = c[0][jn][0 + h], ei = c[0][jn][2 + h];
            float orr = c[1][jn][0 + h], oi = c[1][jn][2 + h];
            float xr = er + orr, xi = ei + oi;
            out[rowK + f] = sqrtf(fmaxf(fmaf(xr, xr, xi * xi), EPSF));
            out[rowK + f + poff] = atan2f(xi + EPSF, xr + EPSF);
            float yr = er - orr, yi = oi - ei;
            out[rowC + f] = sqrtf(fmaxf(fmaf(yr, yr, yi * yi), EPSF));
            out[rowC + f + poff] = atan2f(yi + EPSF, yr + EPSF);
        }
    }
}

extern "C" void kernel_launch(void* const* d_in, const int* in_sizes, int n_in,
                              void* d_out, int out_size) {
    const float* x = (const float*)d_in[0];
    const float* w = (const float*)d_in[1];
    if (n_in >= 2 && in_sizes[0] == 2 * NFREQ * WIN_LEN) {
        w = (const float*)d_in[0];
        x = (const float*)d_in[1];
    }
    float* out = (float*)d_out;

    cudaFuncSetAttribute(stft_mma,
                         cudaFuncAttributeMaxDynamicSharedMemorySize, DYN_SMEM);

    build_A_kernel<<<(MROWS * KK + 255) / 256, 256>>>(w);
    build_XEO_kernel<<<(NBATCH * XESTRIDE + 255) / 256, 256>>>(x);
    k128_kernel<<<dim3((NFRAMES + 7) / 8, NBATCH), 256>>>(x, w, out);
    stft_mma<<<dim3(4, NTILES, NBATCH), NTHREADS, DYN_SMEM>>>(out);
}

// round 17
// speedup vs baseline: 1.7067x; 1.0105x over previous
#include <cuda_runtime.h>
#include <cuda_bf16.h>
#include <math.h>
#include <stdint.h>

#define WIN_LEN 400
#define WIN_INC 100
#define NFREQ   257
#define NBATCH  16
#define NSAMP   160000
#define NFRAMES 1603
#define PADL    300
#define EPSF    1.1920928955078125e-07f

#define KK      224             // padded K per E/O branch (208 real = 13*16)
#define NKC     13              // K chunks of 16
#define MROWS   512             // 128 bins x 4 types (Er,Ei,Or',Oi')
#define NTILES  13              // ceil(1603/128)
#define XESTRIDE 83456
#define NTHREADS 256

#define TILE_B  4096            // 128 rows x 32 bytes (16 bf16)
#define NLVL    3
#define STAGE_B (9 * TILE_B)    // A x3lvl, BE x3lvl, BO x3lvl = 36 KB
#define NSTAGE  3
#define DYN_SMEM (NSTAGE * STAGE_B)   // 108 KB -> 2 CTAs/SM (216 KB)

__device__ __align__(16) __nv_bfloat16 g_A[NLVL][MROWS][KK];
__device__ __align__(16) __nv_bfloat16 g_XE[NLVL][NBATCH][XESTRIDE];
__device__ __align__(16) __nv_bfloat16 g_XO[NLVL][NBATCH][XESTRIDE];

#define ALVL ((size_t)MROWS * KK)
#define XLVL ((size_t)NBATCH * XESTRIDE)

// 32B-row swizzle: unit ^= (row>>2)&1 -> conflict-free ldmatrix phases.
#define SWZ32(row, unit) ((uint32_t)((row) * 32 + (((unit) ^ (((row) >> 2) & 1)) << 4)))

// ---------------- helpers ----------------
__device__ __forceinline__ uint32_t smem_u32(const void* p) {
    uint32_t a;
    asm("{ .reg .u64 t; cvta.to.shared.u64 t, %1; cvt.u32.u64 %0, t; }"
        : "=r"(a) : "l"(p));
    return a;
}
__device__ __forceinline__ void cp16(uint32_t dst, const void* src) {
    asm volatile("cp.async.cg.shared.global [%0], [%1], 16;"
                 :: "r"(dst), "l"(__cvta_generic_to_global(src)) : "memory");
}
__device__ __forceinline__ void cp4(uint32_t dst, const void* src) {
    asm volatile("cp.async.ca.shared.global [%0], [%1], 4;"
                 :: "r"(dst), "l"(__cvta_generic_to_global(src)) : "memory");
}
__device__ __forceinline__ void ldsm4(uint32_t* r, uint32_t addr) {
    asm volatile("ldmatrix.sync.aligned.m8n8.x4.shared.b16 {%0,%1,%2,%3}, [%4];"
                 : "=r"(r[0]), "=r"(r[1]), "=r"(r[2]), "=r"(r[3]) : "r"(addr));
}
__device__ __forceinline__ void mma16816(float* c, const uint32_t* a, const uint32_t* b) {
    asm volatile(
        "mma.sync.aligned.m16n8k16.row.col.f32.bf16.bf16.f32 "
        "{%0,%1,%2,%3}, {%4,%5,%6,%7}, {%8,%9}, {%0,%1,%2,%3};"
        : "+f"(c[0]), "+f"(c[1]), "+f"(c[2]), "+f"(c[3])
        : "r"(a[0]), "r"(a[1]), "r"(a[2]), "r"(a[3]), "r"(b[0]), "r"(b[1]));
}
__device__ __forceinline__ void split3f(float v, __nv_bfloat16* h,
                                        __nv_bfloat16* m, __nv_bfloat16* l) {
    __nv_bfloat16 a = __float2bfloat16(v);
    float r1 = v - __bfloat162float(a);
    __nv_bfloat16 bb = __float2bfloat16(r1);
    *h = a; *m = bb; *l = __float2bfloat16(r1 - __bfloat162float(bb));
}

// ---------------- prep kernels ----------------
// A row m: mx=m>>7; sub=m&127: grp=sub>>5 (32-row group), s2=sub&31; type=s2>>3
// (0 Er, 1 Ei, 2 Or', 3 Oi'); bin j = mx*32 + grp*8 + (s2&7).
// Basis = PROVIDED fp32 weight: E at even samples, O' (twiddle-absorbed) at odd.
__global__ void build_A_kernel(const float* __restrict__ w) {
    int idx = blockIdx.x * blockDim.x + threadIdx.x;
    if (idx >= MROWS * KK) return;
    int m = idx / KK, mk = idx % KK;
    int mx = m >> 7, sub = m & 127;
    int grp = sub >> 5, s2 = sub & 31;
    int type = s2 >> 3;
    int bin = mx * 32 + grp * 8 + (s2 & 7);
    float v = 0.0f;
    if (mk < 200) {
        int n = ((type & 2) ? (2 * mk + 1) : (2 * mk));      // E even / O' odd
        int row = (type & 1) ? (NFREQ + bin) : bin;          // real / imag rows
        v = w[(size_t)row * WIN_LEN + n];
    }
    __nv_bfloat16 h, mm, l;
    split3f(v, &h, &mm, &l);
    g_A[0][m][mk] = h; g_A[1][m][mk] = mm; g_A[2][m][mk] = l;
}

// Decimated padded signals: xe[q] = xpad[2q], xo[q] = xpad[2q+1]; xpad[p]=x[p-300]
__global__ void build_XEO_kernel(const float* __restrict__ x) {
    int idx = blockIdx.x * blockDim.x + threadIdx.x;
    if (idx >= NBATCH * XESTRIDE) return;
    int b = idx / XESTRIDE, q = idx % XESTRIDE;
    const float* xb = x + (size_t)b * NSAMP;
    int se = 2 * q - PADL, so = se + 1;
    float ve = (se >= 0 && se < NSAMP) ? xb[se] : 0.0f;
    float vo = (so >= 0 && so < NSAMP) ? xb[so] : 0.0f;
    __nv_bfloat16 h, mm, l;
    split3f(ve, &h, &mm, &l);
    g_XE[0][b][q] = h; g_XE[1][b][q] = mm; g_XE[2][b][q] = l;
    split3f(vo, &h, &mm, &l);
    g_XO[0][b][q] = h; g_XO[1][b][q] = mm; g_XO[2][b][q] = l;
}

// Bin k=128 via the provided weight rows (128 real, 385 imag). Warp per frame.
__global__ void k128_kernel(const float* __restrict__ x, const float* __restrict__ w,
                            float* __restrict__ out) {
    int wid = threadIdx.x >> 5, lane = threadIdx.x & 31;
    int t = blockIdx.x * 8 + wid;
    int b = blockIdx.y;
    if (t >= NFRAMES) return;
    const float* wr = w + (size_t)128 * WIN_LEN;
    const float* wi = w + (size_t)(NFREQ + 128) * WIN_LEN;
    const float* xb = x + (size_t)b * NSAMP;
    int p0 = t * WIN_INC - PADL;
    float accr = 0.0f, acci = 0.0f;
    for (int n = lane; n < WIN_LEN; n += 32) {
        int p = p0 + n;
        float xv = (p >= 0 && p < NSAMP) ? xb[p] : 0.0f;
        accr = fmaf(xv, __ldg(wr + n), accr);
        acci = fmaf(xv, __ldg(wi + n), acci);
    }
#pragma unroll
    for (int o = 16; o > 0; o >>= 1) {
        accr += __shfl_down_sync(0xFFFFFFFFu, accr, o);
        acci += __shfl_down_sync(0xFFFFFFFFu, acci, o);
    }
    if (lane == 0) {
        float mag = sqrtf(fmaxf(fmaf(accr, accr, acci * acci), EPSF));
        float ph  = atan2f(acci + EPSF, accr + EPSF);
        size_t poff = (size_t)NBATCH * NFREQ * NFRAMES;
        size_t o = ((size_t)b * NFREQ + 128) * NFRAMES + t;
        out[o] = mag;
        out[o + poff] = ph;
    }
}

// ---------------- main MMA kernel ----------------
// Warp partition: mwarp = warp&1 (M=64 rows), nwarp = warp>>1 (N=32 frames).
__global__ void __launch_bounds__(NTHREADS, 2)
stft_mma(float* __restrict__ out) {
    extern __shared__ __align__(128) char smdyn[];
    uint32_t sb = smem_u32(smdyn);
    const int tid = threadIdx.x;
    const int lane = tid & 31, warp = tid >> 5;
    const int mwarp = warp & 1, nwarp = warp >> 1;
    const int mx = blockIdx.x, nt = blockIdx.y, b = blockIdx.z;
    const int m0 = mx * 128, t0 = nt * 128;

    // Loader addressing (same smem layout as R16).
    uint32_t offA; size_t srcA;
    {
        int row = tid >> 1, u = tid & 1;
        offA = SWZ32(row, u);
        srcA = (size_t)(m0 + row) * KK + u * 8;
    }
    uint32_t offB[4]; size_t srcB[4];
#pragma unroll
    for (int it = 0; it < 4; it++) {
        int op = tid + it * NTHREADS;
        int row = op >> 3, g = op & 7;
        offB[it] = SWZ32(row, g >> 2) + ((g & 3) << 2);
        srcB[it] = (size_t)(t0 + row) * 50 + g * 2;
    }
    const __nv_bfloat16* AE = &g_A[0][0][0];
    const __nv_bfloat16* XE = &g_XE[0][b][0];
    const __nv_bfloat16* XO = &g_XO[0][b][0];

#define LOAD_CHUNK(stage, kc) do {                                        \
    uint32_t _st = sb + (stage) * STAGE_B;                                \
    int _k0 = (kc) * 16;                                                  \
    {                                                                     \
        uint32_t d = _st + offA;                                          \
        const __nv_bfloat16* s = AE + srcA + _k0;                         \
        cp16(d,              s);                                          \
        cp16(d + TILE_B,     s + ALVL);                                   \
        cp16(d + 2 * TILE_B, s + 2 * ALVL);                               \
    }                                                                     \
    _Pragma("unroll")                                                     \
    for (int it = 0; it < 4; it++) {                                      \
        uint32_t d = _st + 3 * TILE_B + offB[it];                         \
        size_t so = srcB[it] + _k0;                                       \
        cp4(d,              XE + so);                                     \
        cp4(d + TILE_B,     XE + so + XLVL);                              \
        cp4(d + 2 * TILE_B, XE + so + 2 * XLVL);                          \
        cp4(d + 3 * TILE_B, XO + so);                                     \
        cp4(d + 4 * TILE_B, XO + so + XLVL);                              \
        cp4(d + 5 * TILE_B, XO + so + 2 * XLVL);                          \
    }                                                                     \
    asm volatile("cp.async.commit_group;" ::: "memory");                  \
} while (0)

    // c[eo][g][jn][quad]: eo 0=E,1=O'; g = m16 group within warp; jn = n8 block
    float c[2][2][4][4];
#pragma unroll
    for (int eo = 0; eo < 2; eo++)
#pragma unroll
        for (int g = 0; g < 2; g++)
#pragma unroll
            for (int jn = 0; jn < 4; jn++)
#pragma unroll
                for (int q = 0; q < 4; q++) c[eo][g][jn][q] = 0.0f;

    LOAD_CHUNK(0, 0);
    LOAD_CHUNK(1, 1);

    const int acol  = lane >> 4;                  // A k-half selector
    const int arow_base = mwarp * 64 + (lane & 15);
    const int brow0 = nwarp * 32 + ((lane >> 4) << 3) + (lane & 7);
    const int bksel = (lane >> 3) & 1;

    for (int kc = 0; kc < NKC; kc++) {
        if (kc + 1 < NKC) asm volatile("cp.async.wait_group 1;" ::: "memory");
        else              asm volatile("cp.async.wait_group 0;" ::: "memory");
        __syncthreads();
        if (kc + 2 < NKC) LOAD_CHUNK((kc + 2) % NSTAGE, kc + 2);

        uint32_t st = sb + (kc % NSTAGE) * STAGE_B;
#pragma unroll
        for (int eo = 0; eo < 2; eo++) {
            // A fragments: 2 m16 groups x 3 levels (E rows +0, O rows +16)
            uint32_t af[NLVL][2][4];
#pragma unroll
            for (int g = 0; g < 2; g++) {
                int row = arow_base + g * 32 + eo * 16;
                uint32_t addr = st + SWZ32(row, acol);
#pragma unroll
                for (int lvl = 0; lvl < NLVL; lvl++)
                    ldsm4(af[lvl][g], addr + lvl * TILE_B);
            }
            // B fragments: 2 jp groups (2 n8 each) x 3 levels, from XE or XO
            uint32_t bf[NLVL][2][4];
            uint32_t bbase = st + (3 + eo * 3) * TILE_B;
#pragma unroll
            for (int jp = 0; jp < 2; jp++) {
                int row = brow0 + jp * 16;
                uint32_t addr = bbase + SWZ32(row, bksel);
#pragma unroll
                for (int lvl = 0; lvl < NLVL; lvl++)
                    ldsm4(bf[lvl][jp], addr + lvl * TILE_B);
            }
#pragma unroll
            for (int g = 0; g < 2; g++)
#pragma unroll
                for (int jp = 0; jp < 2; jp++)
#pragma unroll
                    for (int j2 = 0; j2 < 2; j2++) {
                        float* cc = c[eo][g][jp * 2 + j2];
                        mma16816(cc, af[0][g], &bf[0][jp][2 * j2]);   // h*h
                        mma16816(cc, af[0][g], &bf[1][jp][2 * j2]);   // h*m
                        mma16816(cc, af[1][g], &bf[0][jp][2 * j2]);   // m*h
                        mma16816(cc, af[0][g], &bf[2][jp][2 * j2]);   // h*l
                        mma16816(cc, af[2][g], &bf[0][jp][2 * j2]);   // l*h
                        mma16816(cc, af[1][g], &bf[1][jp][2 * j2]);   // m*m
                    }
        }
    }

    // ---- combine (twiddle absorbed in O'): X_j = E + O', X_{256-j} = conj(E - O')
    const size_t poff = (size_t)NBATCH * NFREQ * NFRAMES;
#pragma unroll
    for (int g = 0; g < 2; g++) {
        int k = mx * 32 + mwarp * 16 + g * 8 + (lane >> 2);   // 0..127
        size_t rowK = ((size_t)b * NFREQ + k) * NFRAMES;
        size_t rowC = ((size_t)b * NFREQ + (256 - k)) * NFRAMES;
#pragma unroll
        for (int jn = 0; jn < 4; jn++) {
            int fr = t0 + nwarp * 32 + jn * 8 + ((lane & 3) << 1);
#pragma unroll
            for (int h = 0; h < 2; h++) {
                int f = fr + h;
                if (f >= NFRAMES) continue;
                float er = c[0][g][jn][0 + h], ei = c[0][g][jn][2 + h];
                float orr = c[1][g][jn][0 + h], oi = c[1][g][jn][2 + h];
                float xr = er + orr, xi = ei + oi;
                out[rowK + f] = sqrtf(fmaxf(fmaf(xr, xr, xi * xi), EPSF));
                out[rowK + f + poff] = atan2f(xi + EPSF, xr + EPSF);
                float yr = er - orr, yi = oi - ei;
                out[rowC + f] = sqrtf(fmaxf(fmaf(yr, yr, yi * yi), EPSF));
                out[rowC + f + poff] = atan2f(yi + EPSF, yr + EPSF);
            }
        }
    }
}

extern "C" void kernel_launch(void* const* d_in, const int* in_sizes, int n_in,
                              void* d_out, int out_size) {
    const float* x = (const float*)d_in[0];
    const float* w = (const float*)d_in[1];
    if (n_in >= 2 && in_sizes[0] == 2 * NFREQ * WIN_LEN) {
        w = (const float*)d_in[0];
        x = (const float*)d_in[1];
    }
    float* out = (float*)d_out;

    cudaFuncSetAttribute(stft_mma,
                         cudaFuncAttributeMaxDynamicSharedMemorySize, DYN_SMEM);

    build_A_kernel<<<(MROWS * KK + 255) / 256, 256>>>(w);
    build_XEO_kernel<<<(NBATCH * XESTRIDE + 255) / 256, 256>>>(x);
    k128_kernel<<<dim3((NFRAMES + 7) / 8, NBATCH), 256>>>(x, w, out);
    stft_mma<<<dim3(4, NTILES, NBATCH), NTHREADS, DYN_SMEM>>>(out);
}